// round 12
// baseline (speedup 1.0000x reference)
#include <cuda_runtime.h>
#include <math.h>

#define B_ROWS 131072
#define NEXP   4
#define CH     16      // K-chunk size

typedef unsigned long long ull;

// ---------------- device scratch ------------------------------------------
__device__ int    g_count[NEXP];
__device__ double g_probsum[NEXP];
__device__ float  g_avg[NEXP];
__device__ int    g_bucket[NEXP * B_ROWS];
__device__ float  g_mid[(size_t)B_ROWS * 256];   // attn combined rows (128MB)

// ---------------- f32x2 helpers -------------------------------------------
__device__ __forceinline__ void ffma2(ull& d, ull a, ull b) {
  asm("fma.rn.f32x2 %0, %1, %2, %0;" : "+l"(d) : "l"(a), "l"(b));
}
__device__ __forceinline__ float2 funpack(ull v) {
  float2 f; asm("mov.b64 {%0, %1}, %2;" : "=f"(f.x), "=f"(f.y) : "l"(v)); return f;
}

// ---------------- cp.async helpers ----------------------------------------
__device__ __forceinline__ void cp16(void* sdst, const void* gsrc) {
  unsigned s = (unsigned)__cvta_generic_to_shared(sdst);
  asm volatile("cp.async.cg.shared.global [%0], [%1], 16;\n" :: "r"(s), "l"(gsrc));
}
__device__ __forceinline__ void cp_commit() {
  asm volatile("cp.async.commit_group;\n" ::: "memory");
}
__device__ __forceinline__ void cp_wait1() {
  asm volatile("cp.async.wait_group 1;\n" ::: "memory");
}

// W chunk: CH x 256 floats (16KB). 256 threads, 4 cp16 each.
__device__ __forceinline__ void stage_W(float* Wbuf, const float* Wg, int kc) {
  int t = threadIdx.x;
  const float4* src = (const float4*)(Wg + (size_t)kc * 256);
  #pragma unroll
  for (int i = 0; i < 4; i++)
    cp16(Wbuf + (i * 256 + t) * 4, src + i * 256 + t);
}

// ---------------- packed-FMA chunk ----------------------------------------
// Thread tile: 16 rows x 4 cols (cols col0..col0+3, 2 f32x2 pairs).
// Warp w: rows (w&3)*16..+15, cols (w>>2)*128 + 4*lane .. +3.
// Per k: 1 W LDS.128; per 2k per row: 1 A broadcast LDS.128.
__device__ __forceinline__ void chunk16(
    const ull* __restrict__ Adup, const float* __restrict__ Wb,
    ull (&acc)[16][2], int rbase, int col0)
{
  #pragma unroll
  for (int k2 = 0; k2 < CH / 2; k2++) {
    int k = 2 * k2;
    ulonglong2 w0 = *(const ulonglong2*)(Wb + k * 256 + col0);
    ulonglong2 w1 = *(const ulonglong2*)(Wb + (k + 1) * 256 + col0);
    #pragma unroll
    for (int r = 0; r < 16; r++) {
      ulonglong2 a2 = *(const ulonglong2*)(Adup + (rbase + r) * CH + k);
      ffma2(acc[r][0], a2.x, w0.x);
      ffma2(acc[r][1], a2.x, w0.y);
      ffma2(acc[r][0], a2.y, w1.x);
      ffma2(acc[r][1], a2.y, w1.y);
    }
  }
}

// ---------------- generic GEMM core (ROWS=64) -------------------------------
template<int NC, class F>
__device__ __forceinline__ void gemmT(
    F fetch, const float* __restrict__ Wg,
    ull* Adup, float* Wbuf, ull (&acc)[16][2], int rbase, int col0)
{
  #pragma unroll
  for (int r = 0; r < 16; r++) { acc[r][0] = 0ULL; acc[r][1] = 0ULL; }
  int t = threadIdx.x;
  int ar = t >> 2, aseg = (t & 3) * 4;
  float4 av = fetch(0, ar, aseg);
  stage_W(Wbuf, Wg, 0);             cp_commit();
  stage_W(Wbuf + CH * 256, Wg, CH); cp_commit();
  #pragma unroll 1
  for (int c = 0; c < NC; c++) {
    float4* d = (float4*)(Adup + ar * CH + aseg);
    d[0] = make_float4(av.x, av.x, av.y, av.y);
    d[1] = make_float4(av.z, av.z, av.w, av.w);
    if (c + 1 < NC) av = fetch(c + 1, ar, aseg);
    cp_wait1(); __syncthreads();
    chunk16(Adup, Wbuf + (c & 1) * (CH * 256), acc, rbase, col0);
    __syncthreads();
    if (c + 2 < NC) stage_W(Wbuf + (c & 1) * (CH * 256), Wg, (c + 2) * CH);
    cp_commit();
  }
}

// ---------------- epilogues ------------------------------------------------
template<int ACT>
__device__ __forceinline__ void epi_smem2(
    ull (&acc)[16][2], const float* __restrict__ bias,
    float* Cs, int rbase, int col0)
{
  float4 b = *(const float4*)(bias + col0);
  #pragma unroll
  for (int r = 0; r < 16; r++) {
    float2 v0 = funpack(acc[r][0]), v1 = funpack(acc[r][1]);
    float4 v = make_float4(v0.x + b.x, v0.y + b.y, v1.x + b.z, v1.y + b.w);
    if (ACT == 1) {
      v.x = fmaxf(v.x, 0.f); v.y = fmaxf(v.y, 0.f);
      v.z = fmaxf(v.z, 0.f); v.w = fmaxf(v.w, 0.f);
    }
    if (ACT == 2) {
      v.x = 1.f/(1.f+expf(-v.x)); v.y = 1.f/(1.f+expf(-v.y));
      v.z = 1.f/(1.f+expf(-v.z)); v.w = 1.f/(1.f+expf(-v.w));
    }
    *(float4*)(Cs + (rbase + r) * 256 + col0) = v;
  }
  __syncthreads();
}

__device__ __forceinline__ void epi_gmem2(
    ull (&acc)[16][2], const float* __restrict__ bias,
    float* __restrict__ out, const int* rows, int rbase, int col0, float avg)
{
  float4 b = *(const float4*)(bias + col0);
  #pragma unroll
  for (int r = 0; r < 16; r++) {
    int row = rows[rbase + r];
    if (row < 0) continue;
    float2 v0 = funpack(acc[r][0]), v1 = funpack(acc[r][1]);
    float4 v = make_float4((v0.x + b.x) * avg, (v0.y + b.y) * avg,
                           (v1.x + b.z) * avg, (v1.y + b.w) * avg);
    *(float4*)(out + (size_t)row * 256 + col0) = v;
  }
}

// ---------------- reset / gate / finalize ----------------------------------
__global__ void k_reset() {
  int t = threadIdx.x;
  if (t < NEXP) { g_count[t] = 0; g_probsum[t] = 0.0; }
}

__global__ void __launch_bounds__(256) k_gate(
    const float* __restrict__ zg, const float* __restrict__ zi,
    const float* __restrict__ gW, const float* __restrict__ gb)
{
  __shared__ float  sW[2048];
  __shared__ int    s_cnt[NEXP];
  __shared__ double s_psum[NEXP];
  __shared__ int    s_base[NEXP];
  int tid = threadIdx.x;
  for (int i = tid; i < 2048; i += 256) sW[i] = gW[i];
  if (tid < NEXP) { s_cnt[tid] = 0; s_psum[tid] = 0.0; }
  __syncthreads();

  int lane = tid & 31, warp = tid >> 5;
  int row  = blockIdx.x * 8 + warp;
  const float4* zg4 = (const float4*)(zg + (size_t)row * 256);
  const float4* zi4 = (const float4*)(zi + (size_t)row * 256);
  float a0 = 0.f, a1 = 0.f, a2 = 0.f, a3 = 0.f;
  float4 xs[4];
  xs[0] = zg4[lane]; xs[1] = zg4[lane + 32];
  xs[2] = zi4[lane]; xs[3] = zi4[lane + 32];
  int dbase[4] = { 4 * lane, 128 + 4 * lane, 256 + 4 * lane, 384 + 4 * lane };
  #pragma unroll
  for (int q = 0; q < 4; q++) {
    const float* xv = (const float*)&xs[q];
    #pragma unroll
    for (int j = 0; j < 4; j++) {
      float x = xv[j];
      float4 w = *(const float4*)&sW[(dbase[q] + j) * 4];
      a0 += x * w.x; a1 += x * w.y; a2 += x * w.z; a3 += x * w.w;
    }
  }
  #pragma unroll
  for (int off = 16; off; off >>= 1) {
    a0 += __shfl_down_sync(0xffffffffu, a0, off);
    a1 += __shfl_down_sync(0xffffffffu, a1, off);
    a2 += __shfl_down_sync(0xffffffffu, a2, off);
    a3 += __shfl_down_sync(0xffffffffu, a3, off);
  }
  int myE = 0, myslot = 0;
  if (lane == 0) {
    float l0 = a0 + gb[0], l1 = a1 + gb[1], l2 = a2 + gb[2], l3 = a3 + gb[3];
    float m = fmaxf(fmaxf(l0, l1), fmaxf(l2, l3));
    float s = expf(l0 - m) + expf(l1 - m) + expf(l2 - m) + expf(l3 - m);
    int best = 0; float bl = l0;
    if (l1 > bl) { bl = l1; best = 1; }
    if (l2 > bl) { bl = l2; best = 2; }
    if (l3 > bl) { bl = l3; best = 3; }
    float p = expf(bl - m) / s;
    myslot = atomicAdd(&s_cnt[best], 1);
    atomicAdd(&s_psum[best], (double)p);
    myE = best;
  }
  __syncthreads();
  if (tid < NEXP) {
    s_base[tid] = atomicAdd(&g_count[tid], s_cnt[tid]);
    atomicAdd(&g_probsum[tid], s_psum[tid]);
  }
  __syncthreads();
  if (lane == 0) g_bucket[myE * B_ROWS + s_base[myE] + myslot] = row;
}

__global__ void k_finalize(float* out, int out_size) {
  int t = threadIdx.x;
  if (t < NEXP) {
    int c = g_count[t];
    g_avg[t] = (c > 0) ? (float)(g_probsum[t] / (double)c) : 0.f;
  }
  __syncthreads();
  if (t == 0) {
    float aux = 0.f;
    #pragma unroll
    for (int e = 0; e < NEXP; e++) {
      float u = (float)g_count[e] / (float)B_ROWS;
      aux += u * u;
    }
    aux *= (float)NEXP;
    if (out_size > B_ROWS * 256) out[(size_t)B_ROWS * 256] = aux;
  }
}

// ---------------- expert bodies --------------------------------------------
extern __shared__ float sm[];
#define SMF_HS    0
#define SMF_WBUF  16384
#define SMF_ADUP  24576

// warp mapping: rbase = (warp&3)*16, col0 = (warp>>2)*128 + 4*lane
#define WMAP() \
  int tid = threadIdx.x; \
  int lane = tid & 31, warp = tid >> 5; \
  int rbase = (warp & 3) * 16; \
  int col0 = ((warp >> 2) << 7) + 4 * lane;

// generic 2-layer MLP expert (concat / mul / wsum variants)
template<int MODE>   // 0=concat, 1=mul, 2=wsum
__device__ __forceinline__ void mlp_body(
    int bid, int eid,
    const float* __restrict__ zg, const float* __restrict__ zi,
    const float* __restrict__ W1, const float* __restrict__ b1,
    const float* __restrict__ W2, const float* __restrict__ b2,
    float* __restrict__ out)
{
  int cnt = g_count[eid];
  int base = bid * 64;
  if (base >= cnt) return;
  float avg = g_avg[eid];
  float* Hs   = sm + SMF_HS;
  float* Wbuf = sm + SMF_WBUF;
  ull*   Adup = (ull*)(sm + SMF_ADUP);
  __shared__ int rows_m[64];
  __shared__ const float* ptab_m[128];
  WMAP();
  if (tid < 64) {
    int i = base + tid;
    int row = (i < cnt) ? g_bucket[eid * B_ROWS + i] : -1;
    rows_m[tid] = row;
    size_t rr = (size_t)(row < 0 ? 0 : row) * 256;
    ptab_m[tid]      = zg + rr;
    ptab_m[64 + tid] = zi + rr;
  }
  __syncthreads();
  auto fetchCat = [&](int c, int ar, int aseg) -> float4 {
    int kc = c * CH;
    return *(const float4*)(ptab_m[((kc >> 8) << 6) + ar] + (kc & 255) + aseg);
  };
  auto fetchMul = [&](int c, int ar, int aseg) -> float4 {
    int kc = c * CH;
    float4 g = *(const float4*)(ptab_m[ar] + kc + aseg);
    float4 z = *(const float4*)(ptab_m[64 + ar] + kc + aseg);
    return make_float4(g.x * z.x, g.y * z.y, g.z * z.z, g.w * z.w);
  };
  auto fetchH = [&](int c, int ar, int aseg) -> float4 {
    return *(const float4*)(Hs + ar * 256 + c * CH + aseg);
  };
  auto fetchHW = [&](int c, int ar, int aseg) -> float4 {
    int kc = c * CH;
    float4 a = *(const float4*)(Hs + ar * 256 + kc + aseg);
    float4 g = *(const float4*)(ptab_m[ar] + kc + aseg);
    float4 z = *(const float4*)(ptab_m[64 + ar] + kc + aseg);
    return make_float4(a.x * g.x + (1.f - a.x) * z.x,
                       a.y * g.y + (1.f - a.y) * z.y,
                       a.z * g.z + (1.f - a.z) * z.z,
                       a.w * g.w + (1.f - a.w) * z.w);
  };
  ull acc[16][2];
  if (MODE == 0) {
    gemmT<32>(fetchCat, W1, Adup, Wbuf, acc, rbase, col0);
    epi_smem2<1>(acc, b1, Hs, rbase, col0);
    gemmT<16>(fetchH, W2, Adup, Wbuf, acc, rbase, col0);
  } else if (MODE == 1) {
    gemmT<16>(fetchMul, W1, Adup, Wbuf, acc, rbase, col0);
    epi_smem2<1>(acc, b1, Hs, rbase, col0);
    gemmT<16>(fetchH, W2, Adup, Wbuf, acc, rbase, col0);
  } else {
    gemmT<32>(fetchCat, W1, Adup, Wbuf, acc, rbase, col0);
    epi_smem2<2>(acc, b1, Hs, rbase, col0);   // alpha = sigmoid
    gemmT<16>(fetchHW, W2, Adup, Wbuf, acc, rbase, col0);
  }
  epi_gmem2(acc, b2, out, rows_m, rbase, col0, avg);
}

// attn pass A: 32 pairs (64 token rows), ROWS=64 GEMMs.
__device__ __forceinline__ void attn_bodyA(
    int bid,
    const float* __restrict__ zg, const float* __restrict__ zi,
    const float* __restrict__ Wq, const float* __restrict__ bq,
    const float* __restrict__ Wk, const float* __restrict__ bk,
    const float* __restrict__ Wv, const float* __restrict__ bv)
{
  int cnt = g_count[2];
  int base = bid * 32;                   // pair base
  if (base >= cnt) return;
  float* Qs   = sm + SMF_HS;             // 64 x 256
  float* Wbuf = sm + SMF_WBUF;
  ull*   Adup = (ull*)(sm + SMF_ADUP);
  __shared__ const float* ptab_a[64];
  __shared__ float sc[32][4][2][2];      // [pair][head][t_q][t_k]
  __shared__ float Cf[32 * 8];
  WMAP();
  if (tid < 64) {
    int pair = tid >> 1;
    int i = base + pair;
    int row = (i < cnt) ? g_bucket[2 * B_ROWS + i] : 0;
    size_t rr = (size_t)row * 256;
    ptab_a[tid] = ((tid & 1) ? zi : zg) + rr;
  }
  __syncthreads();

  auto fetchT = [&](int c, int ar, int aseg) -> float4 {
    return *(const float4*)(ptab_a[ar] + c * CH + aseg);
  };

  ull acc[16][2];
  // ---- Q ----
  gemmT<16>(fetchT, Wq, Adup, Wbuf, acc, rbase, col0);
  epi_smem2<0>(acc, bq, Qs, rbase, col0);
  // ---- K (epilogue computes head scores vs Q) ----
  gemmT<16>(fetchT, Wk, Adup, Wbuf, acc, rbase, col0);
  {
    float4 bk4 = *(const float4*)(bk + col0);
    int hh = col0 >> 6;   // head index of this thread's 4 cols (0..3)
    #pragma unroll
    for (int ri = 0; ri < 16; ri++) {
      int r = rbase + ri;
      int p = r >> 1, tk = r & 1;
      float2 v0 = funpack(acc[ri][0]), v1 = funpack(acc[ri][1]);
      float k0 = v0.x + bk4.x, k1 = v0.y + bk4.y;
      float k2 = v1.x + bk4.z, k3 = v1.y + bk4.w;
      #pragma unroll
      for (int tq = 0; tq < 2; tq++) {
        float4 q4 = *(const float4*)(Qs + (2 * p + tq) * 256 + col0);
        float s = k0 * q4.x + k1 * q4.y + k2 * q4.z + k3 * q4.w;
        #pragma unroll
        for (int off = 8; off; off >>= 1)
          s += __shfl_down_sync(0xffffffffu, s, off, 16);
        if ((lane & 15) == 0) sc[p][hh][tq][tk] = s;
      }
    }
  }
  __syncthreads();
  // ---- softmax -> pair coefficients ----
  if (tid < 128) {
    int p = tid >> 2, h = tid & 3;
    const float s = 0.125f;   // 1/sqrt(64)
    float s00 = sc[p][h][0][0] * s, s01 = sc[p][h][0][1] * s;
    float s10 = sc[p][h][1][0] * s, s11 = sc[p][h][1][1] * s;
    float m0 = fmaxf(s00, s01), m1 = fmaxf(s10, s11);
    float e00 = expf(s00 - m0), e01 = expf(s01 - m0);
    float e10 = expf(s10 - m1), e11 = expf(s11 - m1);
    float i0 = 1.f / (e00 + e01), i1 = 1.f / (e10 + e11);
    Cf[p * 8 + h * 2 + 0] = 0.5f * (e00 * i0 + e10 * i1);
    Cf[p * 8 + h * 2 + 1] = 0.5f * (e01 * i0 + e11 * i1);
  }
  __syncthreads();
  // ---- V (epilogue combines pairs -> g_mid) ----
  gemmT<16>(fetchT, Wv, Adup, Wbuf, acc, rbase, col0);
  {
    float4 bv4 = *(const float4*)(bv + col0);
    int hh = col0 >> 6;
    #pragma unroll
    for (int q = 0; q < 8; q++) {
      int p = (rbase >> 1) + q;
      int gp = base + p;
      if (gp >= cnt) continue;
      float c0 = Cf[p * 8 + hh * 2 + 0], c1 = Cf[p * 8 + hh * 2 + 1];
      float2 a00 = funpack(acc[2 * q][0]),     a01 = funpack(acc[2 * q][1]);
      float2 a10 = funpack(acc[2 * q + 1][0]), a11 = funpack(acc[2 * q + 1][1]);
      // coefs sum to 1 -> bias passes straight through
      float4 v = make_float4(c0 * a00.x + c1 * a10.x + bv4.x,
                             c0 * a00.y + c1 * a10.y + bv4.y,
                             c0 * a01.x + c1 * a11.x + bv4.z,
                             c0 * a01.y + c1 * a11.y + bv4.w);
      *(float4*)(g_mid + (size_t)gp * 256 + col0) = v;
    }
  }
}

// ---------------- fused expert kernel --------------------------------------
#define NB_ATTN  (B_ROWS / 32)          // 4096
#define NB_MLP   (B_ROWS / 64)          // 2048

__global__ void __launch_bounds__(256, 2) k_experts(
    const float* __restrict__ zg, const float* __restrict__ zi,
    const float* __restrict__ cW1, const float* __restrict__ cb1,
    const float* __restrict__ cW2, const float* __restrict__ cb2,
    const float* __restrict__ mW1, const float* __restrict__ mb1,
    const float* __restrict__ mW2, const float* __restrict__ mb2,
    const float* __restrict__ aWq, const float* __restrict__ abq,
    const float* __restrict__ aWk, const float* __restrict__ abk,
    const float* __restrict__ aWv, const float* __restrict__ abv,
    const float* __restrict__ wWa, const float* __restrict__ wba,
    const float* __restrict__ wWo, const float* __restrict__ wbo,
    float* __restrict__ out)
{
  int b = blockIdx.x;
  if (b < NB_ATTN) {
    attn_bodyA(b, zg, zi, aWq, abq, aWk, abk, aWv, abv);
  } else if (b < NB_ATTN + NB_MLP) {
    mlp_body<0>(b - NB_ATTN, 0, zg, zi, cW1, cb1, cW2, cb2, out);
  } else if (b < NB_ATTN + 2 * NB_MLP) {
    mlp_body<1>(b - NB_ATTN - NB_MLP, 1, zg, zi, mW1, mb1, mW2, mb2, out);
  } else {
    mlp_body<2>(b - NB_ATTN - 2 * NB_MLP, 3, zg, zi, wWa, wba, wWo, wbo, out);
  }
}

// ---------------- attn pass B: Wo -> Wfc on combined rows -------------------
__global__ void __launch_bounds__(256, 2) k_attn2(
    const float* __restrict__ Wo, const float* __restrict__ bo,
    const float* __restrict__ Wfc, const float* __restrict__ bfc,
    float* __restrict__ out)
{
  int cnt = g_count[2];
  int base = blockIdx.x * 64;
  if (base >= cnt) return;
  float avg = g_avg[2];
  float* Hs   = sm + SMF_HS;
  float* Wbuf = sm + SMF_WBUF;
  ull*   Adup = (ull*)(sm + SMF_ADUP);
  __shared__ int rows_b[64];
  WMAP();
  if (tid < 64) {
    int i = base + tid;
    rows_b[tid] = (i < cnt) ? g_bucket[2 * B_ROWS + i] : -1;
  }
  __syncthreads();
  auto fetchMid = [&](int c, int ar, int aseg) -> float4 {
    return *(const float4*)(g_mid + (size_t)(base + ar) * 256 + c * CH + aseg);
  };
  auto fetchH = [&](int c, int ar, int aseg) -> float4 {
    return *(const float4*)(Hs + ar * 256 + c * CH + aseg);
  };
  ull acc[16][2];
  gemmT<16>(fetchMid, Wo, Adup, Wbuf, acc, rbase, col0);
  epi_smem2<0>(acc, bo, Hs, rbase, col0);
  gemmT<16>(fetchH, Wfc, Adup, Wbuf, acc, rbase, col0);
  epi_gmem2(acc, bfc, out, rows_b, rbase, col0, avg);
}

// ---------------- launch ---------------------------------------------------
extern "C" void kernel_launch(void* const* d_in, const int* in_sizes, int n_in,
                              void* d_out, int out_size) {
  (void)in_sizes; (void)n_in;
  const float* zg  = (const float*)d_in[0];
  const float* zi  = (const float*)d_in[1];
  const float* gW  = (const float*)d_in[2];
  const float* gb  = (const float*)d_in[3];
  const float* cW1 = (const float*)d_in[4];
  const float* cb1 = (const float*)d_in[5];
  const float* cW2 = (const float*)d_in[6];
  const float* cb2 = (const float*)d_in[7];
  const float* mW1 = (const float*)d_in[8];
  const float* mb1 = (const float*)d_in[9];
  const float* mW2 = (const float*)d_in[10];
  const float* mb2 = (const float*)d_in[11];
  const float* aWq = (const float*)d_in[12];
  const float* abq = (const float*)d_in[13];
  const float* aWk = (const float*)d_in[14];
  const float* abk = (const float*)d_in[15];
  const float* aWv = (const float*)d_in[16];
  const float* abv = (const float*)d_in[17];
  const float* aWo = (const float*)d_in[18];
  const float* abo = (const float*)d_in[19];
  const float* aWfc = (const float*)d_in[20];
  const float* abfc = (const float*)d_in[21];
  const float* wWa = (const float*)d_in[22];
  const float* wba = (const float*)d_in[23];
  const float* wWo = (const float*)d_in[24];
  const float* wbo = (const float*)d_in[25];
  float* out = (float*)d_out;

  const int SM_EXP = (16384 + 8192 + 2048) * 4;   // 106496 B

  cudaFuncSetAttribute(k_experts, cudaFuncAttributeMaxDynamicSharedMemorySize, SM_EXP);
  cudaFuncSetAttribute(k_attn2,   cudaFuncAttributeMaxDynamicSharedMemorySize, SM_EXP);

  k_reset<<<1, 32>>>();
  k_gate<<<B_ROWS / 8, 256>>>(zg, zi, gW, gb);
  k_finalize<<<1, 32>>>(out, out_size);
  k_experts<<<NB_ATTN + 3 * NB_MLP, 256, SM_EXP>>>(
      zg, zi, cW1, cb1, cW2, cb2, mW1, mb1, mW2, mb2,
      aWq, abq, aWk, abk, aWv, abv,
      wWa, wba, wWo, wbo, out);
  k_attn2<<<B_ROWS / 64, 256, SM_EXP>>>(aWo, abo, aWfc, abfc, out);
}

// round 13
// speedup vs baseline: 1.0015x; 1.0015x over previous
#include <cuda_runtime.h>
#include <math.h>

#define B_ROWS 131072
#define NEXP   4
#define CH     16      // K-chunk size

typedef unsigned long long ull;

// ---------------- device scratch ------------------------------------------
__device__ int    g_count[NEXP];
__device__ double g_probsum[NEXP];
__device__ float  g_avg[NEXP];
__device__ int    g_bucket[NEXP * B_ROWS];
__device__ float  g_mid[(size_t)B_ROWS * 256];   // attn combined rows (128MB)

// ---------------- f32x2 helpers -------------------------------------------
__device__ __forceinline__ void ffma2(ull& d, ull a, ull b) {
  asm("fma.rn.f32x2 %0, %1, %2, %0;" : "+l"(d) : "l"(a), "l"(b));
}
__device__ __forceinline__ float2 funpack(ull v) {
  float2 f; asm("mov.b64 {%0, %1}, %2;" : "=f"(f.x), "=f"(f.y) : "l"(v)); return f;
}

// ---------------- cp.async helpers ----------------------------------------
__device__ __forceinline__ void cp16(void* sdst, const void* gsrc) {
  unsigned s = (unsigned)__cvta_generic_to_shared(sdst);
  asm volatile("cp.async.cg.shared.global [%0], [%1], 16;\n" :: "r"(s), "l"(gsrc));
}
__device__ __forceinline__ void cp_commit() {
  asm volatile("cp.async.commit_group;\n" ::: "memory");
}
__device__ __forceinline__ void cp_wait1() {
  asm volatile("cp.async.wait_group 1;\n" ::: "memory");
}

// W chunk: CH x 256 floats (16KB). 256 threads, 4 cp16 each.
__device__ __forceinline__ void stage_W(float* Wbuf, const float* Wg, int kc) {
  int t = threadIdx.x;
  const float4* src = (const float4*)(Wg + (size_t)kc * 256);
  #pragma unroll
  for (int i = 0; i < 4; i++)
    cp16(Wbuf + (i * 256 + t) * 4, src + i * 256 + t);
}

// ---------------- packed-FMA chunk ----------------------------------------
// Thread tile: 16 rows x 4 cols (cols col0..col0+3, 2 f32x2 pairs).
// Warp w: rows (w&3)*16..+15, cols (w>>2)*128 + 4*lane .. +3.
// Per k: 1 W LDS.128; per 2k per row: 1 A broadcast LDS.128.
__device__ __forceinline__ void chunk16(
    const ull* __restrict__ Adup, const float* __restrict__ Wb,
    ull (&acc)[16][2], int rbase, int col0)
{
  #pragma unroll
  for (int k2 = 0; k2 < CH / 2; k2++) {
    int k = 2 * k2;
    ulonglong2 w0 = *(const ulonglong2*)(Wb + k * 256 + col0);
    ulonglong2 w1 = *(const ulonglong2*)(Wb + (k + 1) * 256 + col0);
    #pragma unroll
    for (int r = 0; r < 16; r++) {
      ulonglong2 a2 = *(const ulonglong2*)(Adup + (rbase + r) * CH + k);
      ffma2(acc[r][0], a2.x, w0.x);
      ffma2(acc[r][1], a2.x, w0.y);
      ffma2(acc[r][0], a2.y, w1.x);
      ffma2(acc[r][1], a2.y, w1.y);
    }
  }
}

// ---------------- generic GEMM core (ROWS=64) -------------------------------
template<int NC, class F>
__device__ __forceinline__ void gemmT(
    F fetch, const float* __restrict__ Wg,
    ull* Adup, float* Wbuf, ull (&acc)[16][2], int rbase, int col0)
{
  #pragma unroll
  for (int r = 0; r < 16; r++) { acc[r][0] = 0ULL; acc[r][1] = 0ULL; }
  int t = threadIdx.x;
  int ar = t >> 2, aseg = (t & 3) * 4;
  float4 av = fetch(0, ar, aseg);
  stage_W(Wbuf, Wg, 0);             cp_commit();
  stage_W(Wbuf + CH * 256, Wg, CH); cp_commit();
  #pragma unroll 1
  for (int c = 0; c < NC; c++) {
    float4* d = (float4*)(Adup + ar * CH + aseg);
    d[0] = make_float4(av.x, av.x, av.y, av.y);
    d[1] = make_float4(av.z, av.z, av.w, av.w);
    if (c + 1 < NC) av = fetch(c + 1, ar, aseg);
    cp_wait1(); __syncthreads();
    chunk16(Adup, Wbuf + (c & 1) * (CH * 256), acc, rbase, col0);
    __syncthreads();
    if (c + 2 < NC) stage_W(Wbuf + (c & 1) * (CH * 256), Wg, (c + 2) * CH);
    cp_commit();
  }
}

// ---------------- epilogues ------------------------------------------------
template<int ACT>
__device__ __forceinline__ void epi_smem2(
    ull (&acc)[16][2], const float* __restrict__ bias,
    float* Cs, int rbase, int col0)
{
  float4 b = *(const float4*)(bias + col0);
  #pragma unroll
  for (int r = 0; r < 16; r++) {
    float2 v0 = funpack(acc[r][0]), v1 = funpack(acc[r][1]);
    float4 v = make_float4(v0.x + b.x, v0.y + b.y, v1.x + b.z, v1.y + b.w);
    if (ACT == 1) {
      v.x = fmaxf(v.x, 0.f); v.y = fmaxf(v.y, 0.f);
      v.z = fmaxf(v.z, 0.f); v.w = fmaxf(v.w, 0.f);
    }
    if (ACT == 2) {
      v.x = 1.f/(1.f+expf(-v.x)); v.y = 1.f/(1.f+expf(-v.y));
      v.z = 1.f/(1.f+expf(-v.z)); v.w = 1.f/(1.f+expf(-v.w));
    }
    *(float4*)(Cs + (rbase + r) * 256 + col0) = v;
  }
  __syncthreads();
}

__device__ __forceinline__ void epi_gmem2(
    ull (&acc)[16][2], const float* __restrict__ bias,
    float* __restrict__ out, const int* rows, int rbase, int col0, float avg)
{
  float4 b = *(const float4*)(bias + col0);
  #pragma unroll
  for (int r = 0; r < 16; r++) {
    int row = rows[rbase + r];
    if (row < 0) continue;
    float2 v0 = funpack(acc[r][0]), v1 = funpack(acc[r][1]);
    float4 v = make_float4((v0.x + b.x) * avg, (v0.y + b.y) * avg,
                           (v1.x + b.z) * avg, (v1.y + b.w) * avg);
    *(float4*)(out + (size_t)row * 256 + col0) = v;
  }
}

// ---------------- reset / gate / finalize ----------------------------------
__global__ void k_reset() {
  int t = threadIdx.x;
  if (t < NEXP) { g_count[t] = 0; g_probsum[t] = 0.0; }
}

__global__ void __launch_bounds__(256) k_gate(
    const float* __restrict__ zg, const float* __restrict__ zi,
    const float* __restrict__ gW, const float* __restrict__ gb)
{
  __shared__ float  sW[2048];
  __shared__ int    s_cnt[NEXP];
  __shared__ double s_psum[NEXP];
  __shared__ int    s_base[NEXP];
  int tid = threadIdx.x;
  for (int i = tid; i < 2048; i += 256) sW[i] = gW[i];
  if (tid < NEXP) { s_cnt[tid] = 0; s_psum[tid] = 0.0; }
  __syncthreads();

  int lane = tid & 31, warp = tid >> 5;
  int row  = blockIdx.x * 8 + warp;
  const float4* zg4 = (const float4*)(zg + (size_t)row * 256);
  const float4* zi4 = (const float4*)(zi + (size_t)row * 256);
  float a0 = 0.f, a1 = 0.f, a2 = 0.f, a3 = 0.f;
  float4 xs[4];
  xs[0] = zg4[lane]; xs[1] = zg4[lane + 32];
  xs[2] = zi4[lane]; xs[3] = zi4[lane + 32];
  int dbase[4] = { 4 * lane, 128 + 4 * lane, 256 + 4 * lane, 384 + 4 * lane };
  #pragma unroll
  for (int q = 0; q < 4; q++) {
    const float* xv = (const float*)&xs[q];
    #pragma unroll
    for (int j = 0; j < 4; j++) {
      float x = xv[j];
      float4 w = *(const float4*)&sW[(dbase[q] + j) * 4];
      a0 += x * w.x; a1 += x * w.y; a2 += x * w.z; a3 += x * w.w;
    }
  }
  #pragma unroll
  for (int off = 16; off; off >>= 1) {
    a0 += __shfl_down_sync(0xffffffffu, a0, off);
    a1 += __shfl_down_sync(0xffffffffu, a1, off);
    a2 += __shfl_down_sync(0xffffffffu, a2, off);
    a3 += __shfl_down_sync(0xffffffffu, a3, off);
  }
  int myE = 0, myslot = 0;
  if (lane == 0) {
    float l0 = a0 + gb[0], l1 = a1 + gb[1], l2 = a2 + gb[2], l3 = a3 + gb[3];
    float m = fmaxf(fmaxf(l0, l1), fmaxf(l2, l3));
    float s = expf(l0 - m) + expf(l1 - m) + expf(l2 - m) + expf(l3 - m);
    int best = 0; float bl = l0;
    if (l1 > bl) { bl = l1; best = 1; }
    if (l2 > bl) { bl = l2; best = 2; }
    if (l3 > bl) { bl = l3; best = 3; }
    float p = expf(bl - m) / s;
    myslot = atomicAdd(&s_cnt[best], 1);
    atomicAdd(&s_psum[best], (double)p);
    myE = best;
  }
  __syncthreads();
  if (tid < NEXP) {
    s_base[tid] = atomicAdd(&g_count[tid], s_cnt[tid]);
    atomicAdd(&g_probsum[tid], s_psum[tid]);
  }
  __syncthreads();
  if (lane == 0) g_bucket[myE * B_ROWS + s_base[myE] + myslot] = row;
}

__global__ void k_finalize(float* out, int out_size) {
  int t = threadIdx.x;
  if (t < NEXP) {
    int c = g_count[t];
    g_avg[t] = (c > 0) ? (float)(g_probsum[t] / (double)c) : 0.f;
  }
  __syncthreads();
  if (t == 0) {
    float aux = 0.f;
    #pragma unroll
    for (int e = 0; e < NEXP; e++) {
      float u = (float)g_count[e] / (float)B_ROWS;
      aux += u * u;
    }
    aux *= (float)NEXP;
    if (out_size > B_ROWS * 256) out[(size_t)B_ROWS * 256] = aux;
  }
}

// ---------------- expert bodies --------------------------------------------
extern __shared__ float sm[];
#define SMF_HS    0
#define SMF_WBUF  16384
#define SMF_ADUP  24576

// warp mapping: rbase = (warp&3)*16, col0 = (warp>>2)*128 + 4*lane
#define WMAP() \
  int tid = threadIdx.x; \
  int lane = tid & 31, warp = tid >> 5; \
  int rbase = (warp & 3) * 16; \
  int col0 = ((warp >> 2) << 7) + 4 * lane;

// generic 2-layer MLP expert (concat / mul / wsum variants)
template<int MODE>   // 0=concat, 1=mul, 2=wsum
__device__ __forceinline__ void mlp_body(
    int bid, int eid,
    const float* __restrict__ zg, const float* __restrict__ zi,
    const float* __restrict__ W1, const float* __restrict__ b1,
    const float* __restrict__ W2, const float* __restrict__ b2,
    float* __restrict__ out)
{
  int cnt = g_count[eid];
  int base = bid * 64;
  if (base >= cnt) return;
  float avg = g_avg[eid];
  float* Hs   = sm + SMF_HS;
  float* Wbuf = sm + SMF_WBUF;
  ull*   Adup = (ull*)(sm + SMF_ADUP);
  __shared__ int rows_m[64];
  __shared__ const float* ptab_m[128];
  WMAP();
  if (tid < 64) {
    int i = base + tid;
    int row = (i < cnt) ? g_bucket[eid * B_ROWS + i] : -1;
    rows_m[tid] = row;
    size_t rr = (size_t)(row < 0 ? 0 : row) * 256;
    ptab_m[tid]      = zg + rr;
    ptab_m[64 + tid] = zi + rr;
  }
  __syncthreads();
  auto fetchCat = [&](int c, int ar, int aseg) -> float4 {
    int kc = c * CH;
    return *(const float4*)(ptab_m[((kc >> 8) << 6) + ar] + (kc & 255) + aseg);
  };
  auto fetchMul = [&](int c, int ar, int aseg) -> float4 {
    int kc = c * CH;
    float4 g = *(const float4*)(ptab_m[ar] + kc + aseg);
    float4 z = *(const float4*)(ptab_m[64 + ar] + kc + aseg);
    return make_float4(g.x * z.x, g.y * z.y, g.z * z.z, g.w * z.w);
  };
  auto fetchH = [&](int c, int ar, int aseg) -> float4 {
    return *(const float4*)(Hs + ar * 256 + c * CH + aseg);
  };
  auto fetchHW = [&](int c, int ar, int aseg) -> float4 {
    int kc = c * CH;
    float4 a = *(const float4*)(Hs + ar * 256 + kc + aseg);
    float4 g = *(const float4*)(ptab_m[ar] + kc + aseg);
    float4 z = *(const float4*)(ptab_m[64 + ar] + kc + aseg);
    return make_float4(a.x * g.x + (1.f - a.x) * z.x,
                       a.y * g.y + (1.f - a.y) * z.y,
                       a.z * g.z + (1.f - a.z) * z.z,
                       a.w * g.w + (1.f - a.w) * z.w);
  };
  ull acc[16][2];
  if (MODE == 0) {
    gemmT<32>(fetchCat, W1, Adup, Wbuf, acc, rbase, col0);
    epi_smem2<1>(acc, b1, Hs, rbase, col0);
    gemmT<16>(fetchH, W2, Adup, Wbuf, acc, rbase, col0);
  } else if (MODE == 1) {
    gemmT<16>(fetchMul, W1, Adup, Wbuf, acc, rbase, col0);
    epi_smem2<1>(acc, b1, Hs, rbase, col0);
    gemmT<16>(fetchH, W2, Adup, Wbuf, acc, rbase, col0);
  } else {
    gemmT<32>(fetchCat, W1, Adup, Wbuf, acc, rbase, col0);
    epi_smem2<2>(acc, b1, Hs, rbase, col0);   // alpha = sigmoid
    gemmT<16>(fetchHW, W2, Adup, Wbuf, acc, rbase, col0);
  }
  epi_gmem2(acc, b2, out, rows_m, rbase, col0, avg);
}

// attn pass A: 32 pairs (64 token rows), ROWS=64 GEMMs.
__device__ __forceinline__ void attn_bodyA(
    int bid,
    const float* __restrict__ zg, const float* __restrict__ zi,
    const float* __restrict__ Wq, const float* __restrict__ bq,
    const float* __restrict__ Wk, const float* __restrict__ bk,
    const float* __restrict__ Wv, const float* __restrict__ bv)
{
  int cnt = g_count[2];
  int base = bid * 32;                   // pair base
  if (base >= cnt) return;
  float* Qs   = sm + SMF_HS;             // 64 x 256
  float* Wbuf = sm + SMF_WBUF;
  ull*   Adup = (ull*)(sm + SMF_ADUP);
  __shared__ const float* ptab_a[64];
  __shared__ float sc[32][4][2][2];      // [pair][head][t_q][t_k]
  __shared__ float Cf[32 * 8];
  WMAP();
  if (tid < 64) {
    int pair = tid >> 1;
    int i = base + pair;
    int row = (i < cnt) ? g_bucket[2 * B_ROWS + i] : 0;
    size_t rr = (size_t)row * 256;
    ptab_a[tid] = ((tid & 1) ? zi : zg) + rr;
  }
  __syncthreads();

  auto fetchT = [&](int c, int ar, int aseg) -> float4 {
    return *(const float4*)(ptab_a[ar] + c * CH + aseg);
  };

  ull acc[16][2];
  // ---- Q ----
  gemmT<16>(fetchT, Wq, Adup, Wbuf, acc, rbase, col0);
  epi_smem2<0>(acc, bq, Qs, rbase, col0);
  // ---- K (epilogue computes head scores vs Q) ----
  gemmT<16>(fetchT, Wk, Adup, Wbuf, acc, rbase, col0);
  {
    float4 bk4 = *(const float4*)(bk + col0);
    int hh = col0 >> 6;   // head index of this thread's 4 cols (0..3)
    #pragma unroll
    for (int ri = 0; ri < 16; ri++) {
      int r = rbase + ri;
      int p = r >> 1, tk = r & 1;
      float2 v0 = funpack(acc[ri][0]), v1 = funpack(acc[ri][1]);
      float k0 = v0.x + bk4.x, k1 = v0.y + bk4.y;
      float k2 = v1.x + bk4.z, k3 = v1.y + bk4.w;
      #pragma unroll
      for (int tq = 0; tq < 2; tq++) {
        float4 q4 = *(const float4*)(Qs + (2 * p + tq) * 256 + col0);
        float s = k0 * q4.x + k1 * q4.y + k2 * q4.z + k3 * q4.w;
        #pragma unroll
        for (int off = 8; off; off >>= 1)
          s += __shfl_down_sync(0xffffffffu, s, off, 16);
        if ((lane & 15) == 0) sc[p][hh][tq][tk] = s;
      }
    }
  }
  __syncthreads();
  // ---- softmax -> pair coefficients ----
  if (tid < 128) {
    int p = tid >> 2, h = tid & 3;
    const float s = 0.125f;   // 1/sqrt(64)
    float s00 = sc[p][h][0][0] * s, s01 = sc[p][h][0][1] * s;
    float s10 = sc[p][h][1][0] * s, s11 = sc[p][h][1][1] * s;
    float m0 = fmaxf(s00, s01), m1 = fmaxf(s10, s11);
    float e00 = expf(s00 - m0), e01 = expf(s01 - m0);
    float e10 = expf(s10 - m1), e11 = expf(s11 - m1);
    float i0 = 1.f / (e00 + e01), i1 = 1.f / (e10 + e11);
    Cf[p * 8 + h * 2 + 0] = 0.5f * (e00 * i0 + e10 * i1);
    Cf[p * 8 + h * 2 + 1] = 0.5f * (e01 * i0 + e11 * i1);
  }
  __syncthreads();
  // ---- V (epilogue combines pairs -> g_mid) ----
  gemmT<16>(fetchT, Wv, Adup, Wbuf, acc, rbase, col0);
  {
    float4 bv4 = *(const float4*)(bv + col0);
    int hh = col0 >> 6;
    #pragma unroll
    for (int q = 0; q < 8; q++) {
      int p = (rbase >> 1) + q;
      int gp = base + p;
      if (gp >= cnt) continue;
      float c0 = Cf[p * 8 + hh * 2 + 0], c1 = Cf[p * 8 + hh * 2 + 1];
      float2 a00 = funpack(acc[2 * q][0]),     a01 = funpack(acc[2 * q][1]);
      float2 a10 = funpack(acc[2 * q + 1][0]), a11 = funpack(acc[2 * q + 1][1]);
      // coefs sum to 1 -> bias passes straight through
      float4 v = make_float4(c0 * a00.x + c1 * a10.x + bv4.x,
                             c0 * a00.y + c1 * a10.y + bv4.y,
                             c0 * a01.x + c1 * a11.x + bv4.z,
                             c0 * a01.y + c1 * a11.y + bv4.w);
      *(float4*)(g_mid + (size_t)gp * 256 + col0) = v;
    }
  }
}

// ---------------- fused expert kernel --------------------------------------
#define NB_ATTN  (B_ROWS / 32)          // 4096
#define NB_MLP   (B_ROWS / 64)          // 2048

__global__ void __launch_bounds__(256, 2) k_experts(
    const float* __restrict__ zg, const float* __restrict__ zi,
    const float* __restrict__ cW1, const float* __restrict__ cb1,
    const float* __restrict__ cW2, const float* __restrict__ cb2,
    const float* __restrict__ mW1, const float* __restrict__ mb1,
    const float* __restrict__ mW2, const float* __restrict__ mb2,
    const float* __restrict__ aWq, const float* __restrict__ abq,
    const float* __restrict__ aWk, const float* __restrict__ abk,
    const float* __restrict__ aWv, const float* __restrict__ abv,
    const float* __restrict__ wWa, const float* __restrict__ wba,
    const float* __restrict__ wWo, const float* __restrict__ wbo,
    float* __restrict__ out)
{
  int b = blockIdx.x;
  if (b < NB_ATTN) {
    attn_bodyA(b, zg, zi, aWq, abq, aWk, abk, aWv, abv);
  } else if (b < NB_ATTN + NB_MLP) {
    mlp_body<0>(b - NB_ATTN, 0, zg, zi, cW1, cb1, cW2, cb2, out);
  } else if (b < NB_ATTN + 2 * NB_MLP) {
    mlp_body<1>(b - NB_ATTN - NB_MLP, 1, zg, zi, mW1, mb1, mW2, mb2, out);
  } else {
    mlp_body<2>(b - NB_ATTN - 2 * NB_MLP, 3, zg, zi, wWa, wba, wWo, wbo, out);
  }
}

// ---------------- attn pass B: Wo -> Wfc on combined rows -------------------
__global__ void __launch_bounds__(256, 2) k_attn2(
    const float* __restrict__ Wo, const float* __restrict__ bo,
    const float* __restrict__ Wfc, const float* __restrict__ bfc,
    float* __restrict__ out)
{
  int cnt = g_count[2];
  int base = blockIdx.x * 64;
  if (base >= cnt) return;
  float avg = g_avg[2];
  float* Hs   = sm + SMF_HS;
  float* Wbuf = sm + SMF_WBUF;
  ull*   Adup = (ull*)(sm + SMF_ADUP);
  __shared__ int rows_b[64];
  WMAP();
  if (tid < 64) {
    int i = base + tid;
    rows_b[tid] = (i < cnt) ? g_bucket[2 * B_ROWS + i] : -1;
  }
  __syncthreads();
  auto fetchMid = [&](int c, int ar, int aseg) -> float4 {
    return *(const float4*)(g_mid + (size_t)(base + ar) * 256 + c * CH + aseg);
  };
  auto fetchH = [&](int c, int ar, int aseg) -> float4 {
    return *(const float4*)(Hs + ar * 256 + c * CH + aseg);
  };
  ull acc[16][2];
  gemmT<16>(fetchMid, Wo, Adup, Wbuf, acc, rbase, col0);
  epi_smem2<0>(acc, bo, Hs, rbase, col0);
  gemmT<16>(fetchH, Wfc, Adup, Wbuf, acc, rbase, col0);
  epi_gmem2(acc, bfc, out, rows_b, rbase, col0, avg);
}

// ---------------- launch ---------------------------------------------------
extern "C" void kernel_launch(void* const* d_in, const int* in_sizes, int n_in,
                              void* d_out, int out_size) {
  (void)in_sizes; (void)n_in;
  const float* zg  = (const float*)d_in[0];
  const float* zi  = (const float*)d_in[1];
  const float* gW  = (const float*)d_in[2];
  const float* gb  = (const float*)d_in[3];
  const float* cW1 = (const float*)d_in[4];
  const float* cb1 = (const float*)d_in[5];
  const float* cW2 = (const float*)d_in[6];
  const float* cb2 = (const float*)d_in[7];
  const float* mW1 = (const float*)d_in[8];
  const float* mb1 = (const float*)d_in[9];
  const float* mW2 = (const float*)d_in[10];
  const float* mb2 = (const float*)d_in[11];
  const float* aWq = (const float*)d_in[12];
  const float* abq = (const float*)d_in[13];
  const float* aWk = (const float*)d_in[14];
  const float* abk = (const float*)d_in[15];
  const float* aWv = (const float*)d_in[16];
  const float* abv = (const float*)d_in[17];
  const float* aWo = (const float*)d_in[18];
  const float* abo = (const float*)d_in[19];
  const float* aWfc = (const float*)d_in[20];
  const float* abfc = (const float*)d_in[21];
  const float* wWa = (const float*)d_in[22];
  const float* wba = (const float*)d_in[23];
  const float* wWo = (const float*)d_in[24];
  const float* wbo = (const float*)d_in[25];
  float* out = (float*)d_out;

  const int SM_EXP = (16384 + 8192 + 2048) * 4;   // 106496 B

  cudaFuncSetAttribute(k_experts, cudaFuncAttributeMaxDynamicSharedMemorySize, SM_EXP);
  cudaFuncSetAttribute(k_attn2,   cudaFuncAttributeMaxDynamicSharedMemorySize, SM_EXP);

  k_reset<<<1, 32>>>();
  k_gate<<<B_ROWS / 8, 256>>>(zg, zi, gW, gb);
  k_finalize<<<1, 32>>>(out, out_size);
  k_experts<<<NB_ATTN + 3 * NB_MLP, 256, SM_EXP>>>(
      zg, zi, cW1, cb1, cW2, cb2, mW1, mb1, mW2, mb2,
      aWq, abq, aWk, abk, aWv, abv,
      wWa, wba, wWo, wbo, out);
  k_attn2<<<B_ROWS / 64, 256, SM_EXP>>>(aWo, abo, aWfc, abfc, out);
}

// round 16
// speedup vs baseline: 1.0948x; 1.0931x over previous
#include <cuda_runtime.h>
#include <math.h>

#define B_ROWS 131072
#define NEXP   4
#define CH     16      // K-chunk size

typedef unsigned long long ull;

// ---------------- device scratch ------------------------------------------
__device__ int    g_count[NEXP];
__device__ double g_probsum[NEXP];
__device__ float  g_avg[NEXP];
__device__ int    g_bucket[NEXP * B_ROWS];

// ---------------- f32x2 helpers -------------------------------------------
__device__ __forceinline__ void ffma2(ull& d, ull a, ull b) {
  asm("fma.rn.f32x2 %0, %1, %2, %0;" : "+l"(d) : "l"(a), "l"(b));
}
__device__ __forceinline__ float2 funpack(ull v) {
  float2 f; asm("mov.b64 {%0, %1}, %2;" : "=f"(f.x), "=f"(f.y) : "l"(v)); return f;
}

// ---------------- cp.async helpers ----------------------------------------
__device__ __forceinline__ void cp16(void* sdst, const void* gsrc) {
  unsigned s = (unsigned)__cvta_generic_to_shared(sdst);
  asm volatile("cp.async.cg.shared.global [%0], [%1], 16;\n" :: "r"(s), "l"(gsrc));
}
__device__ __forceinline__ void cp_commit() {
  asm volatile("cp.async.commit_group;\n" ::: "memory");
}
__device__ __forceinline__ void cp_wait1() {
  asm volatile("cp.async.wait_group 1;\n" ::: "memory");
}

// W chunk: CH x 256 floats (16KB). 256 threads, 4 cp16 each.
__device__ __forceinline__ void stage_W(float* Wbuf, const float* Wg, int kc) {
  int t = threadIdx.x;
  const float4* src = (const float4*)(Wg + (size_t)kc * 256);
  #pragma unroll
  for (int i = 0; i < 4; i++)
    cp16(Wbuf + (i * 256 + t) * 4, src + i * 256 + t);
}

// ---------------- packed-FMA chunk (R10 winner: 8 rows x 8 cols/thread) ----
template<int NR>
__device__ __forceinline__ void chunk2(
    const ull* __restrict__ Adup, const float* __restrict__ Wb,
    ull (&acc)[NR][4], int rbase, int lane)
{
  #pragma unroll
  for (int k2 = 0; k2 < CH / 2; k2++) {
    int k = 2 * k2;
    ulonglong2 w0lo = *(const ulonglong2*)(Wb + k * 256 + 4 * lane);
    ulonglong2 w0hi = *(const ulonglong2*)(Wb + k * 256 + 4 * lane + 128);
    ulonglong2 w1lo = *(const ulonglong2*)(Wb + (k + 1) * 256 + 4 * lane);
    ulonglong2 w1hi = *(const ulonglong2*)(Wb + (k + 1) * 256 + 4 * lane + 128);
    #pragma unroll
    for (int r = 0; r < NR; r++) {
      ulonglong2 a2 = *(const ulonglong2*)(Adup + (rbase + r) * CH + k);
      ffma2(acc[r][0], a2.x, w0lo.x);
      ffma2(acc[r][1], a2.x, w0lo.y);
      ffma2(acc[r][2], a2.x, w0hi.x);
      ffma2(acc[r][3], a2.x, w0hi.y);
      ffma2(acc[r][0], a2.y, w1lo.x);
      ffma2(acc[r][1], a2.y, w1lo.y);
      ffma2(acc[r][2], a2.y, w1hi.x);
      ffma2(acc[r][3], a2.y, w1hi.y);
    }
  }
}

// ---------------- generic GEMM core ----------------------------------------
template<int ROWS, int NC, class F>
__device__ __forceinline__ void gemmT(
    F fetch, const float* __restrict__ Wg,
    ull* Adup, float* Wbuf, ull (&acc)[ROWS / 8][4], int rbase, int lane)
{
  constexpr int NR = ROWS / 8;
  #pragma unroll
  for (int r = 0; r < NR; r++)
    #pragma unroll
    for (int c = 0; c < 4; c++) acc[r][c] = 0ULL;
  int t = threadIdx.x;
  int ar = t >> 2, aseg = (t & 3) * 4;
  bool act = (ar < ROWS);
  float4 av = make_float4(0.f, 0.f, 0.f, 0.f);
  if (act) av = fetch(0, ar, aseg);
  stage_W(Wbuf, Wg, 0);             cp_commit();
  stage_W(Wbuf + CH * 256, Wg, CH); cp_commit();
  #pragma unroll 1
  for (int c = 0; c < NC; c++) {
    if (act) {
      float4* d = (float4*)(Adup + ar * CH + aseg);
      d[0] = make_float4(av.x, av.x, av.y, av.y);
      d[1] = make_float4(av.z, av.z, av.w, av.w);
      if (c + 1 < NC) av = fetch(c + 1, ar, aseg);
    }
    cp_wait1(); __syncthreads();
    chunk2<NR>(Adup, Wbuf + (c & 1) * (CH * 256), acc, rbase, lane);
    __syncthreads();
    if (c + 2 < NC) stage_W(Wbuf + (c & 1) * (CH * 256), Wg, (c + 2) * CH);
    cp_commit();
  }
}

// ---------------- epilogues ------------------------------------------------
template<int NR, int ACT>
__device__ __forceinline__ void epi_smem2(
    ull (&acc)[NR][4], const float* __restrict__ bias,
    float* Cs, int rbase, int lane)
{
  float4 blo = *(const float4*)(bias + 4 * lane);
  float4 bhi = *(const float4*)(bias + 4 * lane + 128);
  #pragma unroll
  for (int r = 0; r < NR; r++) {
    float2 v0 = funpack(acc[r][0]), v1 = funpack(acc[r][1]);
    float2 v2 = funpack(acc[r][2]), v3 = funpack(acc[r][3]);
    float4 lo = make_float4(v0.x + blo.x, v0.y + blo.y, v1.x + blo.z, v1.y + blo.w);
    float4 hi = make_float4(v2.x + bhi.x, v2.y + bhi.y, v3.x + bhi.z, v3.y + bhi.w);
    if (ACT == 1) {
      lo.x = fmaxf(lo.x, 0.f); lo.y = fmaxf(lo.y, 0.f); lo.z = fmaxf(lo.z, 0.f); lo.w = fmaxf(lo.w, 0.f);
      hi.x = fmaxf(hi.x, 0.f); hi.y = fmaxf(hi.y, 0.f); hi.z = fmaxf(hi.z, 0.f); hi.w = fmaxf(hi.w, 0.f);
    }
    if (ACT == 2) {
      lo.x = 1.f/(1.f+expf(-lo.x)); lo.y = 1.f/(1.f+expf(-lo.y));
      lo.z = 1.f/(1.f+expf(-lo.z)); lo.w = 1.f/(1.f+expf(-lo.w));
      hi.x = 1.f/(1.f+expf(-hi.x)); hi.y = 1.f/(1.f+expf(-hi.y));
      hi.z = 1.f/(1.f+expf(-hi.z)); hi.w = 1.f/(1.f+expf(-hi.w));
    }
    *(float4*)(Cs + (rbase + r) * 256 + 4 * lane) = lo;
    *(float4*)(Cs + (rbase + r) * 256 + 4 * lane + 128) = hi;
  }
  __syncthreads();
}

template<int NR>
__device__ __forceinline__ void epi_gmem2(
    ull (&acc)[NR][4], const float* __restrict__ bias,
    float* __restrict__ out, const int* rows, int rbase, int lane, float avg)
{
  float4 blo = *(const float4*)(bias + 4 * lane);
  float4 bhi = *(const float4*)(bias + 4 * lane + 128);
  #pragma unroll
  for (int r = 0; r < NR; r++) {
    int row = rows[rbase + r];
    if (row < 0) continue;
    float2 v0 = funpack(acc[r][0]), v1 = funpack(acc[r][1]);
    float2 v2 = funpack(acc[r][2]), v3 = funpack(acc[r][3]);
    float4 lo = make_float4((v0.x + blo.x) * avg, (v0.y + blo.y) * avg,
                            (v1.x + blo.z) * avg, (v1.y + blo.w) * avg);
    float4 hi = make_float4((v2.x + bhi.x) * avg, (v2.y + bhi.y) * avg,
                            (v3.x + bhi.z) * avg, (v3.y + bhi.w) * avg);
    *(float4*)(out + (size_t)row * 256 + 4 * lane) = lo;
    *(float4*)(out + (size_t)row * 256 + 4 * lane + 128) = hi;
  }
}

// ---------------- reset / gate / finalize ----------------------------------
__global__ void k_reset() {
  int t = threadIdx.x;
  if (t < NEXP) { g_count[t] = 0; g_probsum[t] = 0.0; }
}

__global__ void __launch_bounds__(256) k_gate(
    const float* __restrict__ zg, const float* __restrict__ zi,
    const float* __restrict__ gW, const float* __restrict__ gb)
{
  __shared__ float  sW[2048];
  __shared__ int    s_cnt[NEXP];
  __shared__ double s_psum[NEXP];
  __shared__ int    s_base[NEXP];
  int tid = threadIdx.x;
  for (int i = tid; i < 2048; i += 256) sW[i] = gW[i];
  if (tid < NEXP) { s_cnt[tid] = 0; s_psum[tid] = 0.0; }
  __syncthreads();

  int lane = tid & 31, warp = tid >> 5;
  int row  = blockIdx.x * 8 + warp;
  const float4* zg4 = (const float4*)(zg + (size_t)row * 256);
  const float4* zi4 = (const float4*)(zi + (size_t)row * 256);
  float a0 = 0.f, a1 = 0.f, a2 = 0.f, a3 = 0.f;
  float4 xs[4];
  xs[0] = zg4[lane]; xs[1] = zg4[lane + 32];
  xs[2] = zi4[lane]; xs[3] = zi4[lane + 32];
  int dbase[4] = { 4 * lane, 128 + 4 * lane, 256 + 4 * lane, 384 + 4 * lane };
  #pragma unroll
  for (int q = 0; q < 4; q++) {
    const float* xv = (const float*)&xs[q];
    #pragma unroll
    for (int j = 0; j < 4; j++) {
      float x = xv[j];
      float4 w = *(const float4*)&sW[(dbase[q] + j) * 4];
      a0 += x * w.x; a1 += x * w.y; a2 += x * w.z; a3 += x * w.w;
    }
  }
  #pragma unroll
  for (int off = 16; off; off >>= 1) {
    a0 += __shfl_down_sync(0xffffffffu, a0, off);
    a1 += __shfl_down_sync(0xffffffffu, a1, off);
    a2 += __shfl_down_sync(0xffffffffu, a2, off);
    a3 += __shfl_down_sync(0xffffffffu, a3, off);
  }
  int myE = 0, myslot = 0;
  if (lane == 0) {
    float l0 = a0 + gb[0], l1 = a1 + gb[1], l2 = a2 + gb[2], l3 = a3 + gb[3];
    float m = fmaxf(fmaxf(l0, l1), fmaxf(l2, l3));
    float s = expf(l0 - m) + expf(l1 - m) + expf(l2 - m) + expf(l3 - m);
    int best = 0; float bl = l0;
    if (l1 > bl) { bl = l1; best = 1; }
    if (l2 > bl) { bl = l2; best = 2; }
    if (l3 > bl) { bl = l3; best = 3; }
    float p = expf(bl - m) / s;
    myslot = atomicAdd(&s_cnt[best], 1);
    atomicAdd(&s_psum[best], (double)p);
    myE = best;
  }
  __syncthreads();
  if (tid < NEXP) {
    s_base[tid] = atomicAdd(&g_count[tid], s_cnt[tid]);
    atomicAdd(&g_probsum[tid], s_psum[tid]);
  }
  __syncthreads();
  if (lane == 0) g_bucket[myE * B_ROWS + s_base[myE] + myslot] = row;
}

__global__ void k_finalize(float* out, int out_size) {
  int t = threadIdx.x;
  if (t < NEXP) {
    int c = g_count[t];
    g_avg[t] = (c > 0) ? (float)(g_probsum[t] / (double)c) : 0.f;
  }
  __syncthreads();
  if (t == 0) {
    float aux = 0.f;
    #pragma unroll
    for (int e = 0; e < NEXP; e++) {
      float u = (float)g_count[e] / (float)B_ROWS;
      aux += u * u;
    }
    aux *= (float)NEXP;
    if (out_size > B_ROWS * 256) out[(size_t)B_ROWS * 256] = aux;
  }
}

// ---------------- expert bodies --------------------------------------------
extern __shared__ float sm[];
#define SMF_HS    0
#define SMF_WBUF  16384
#define SMF_ADUP  24576

// generic 2-layer MLP expert (concat / mul / wsum variants)
template<int MODE>   // 0=concat, 1=mul, 2=wsum
__device__ __forceinline__ void mlp_body(
    int bid, int eid,
    const float* __restrict__ zg, const float* __restrict__ zi,
    const float* __restrict__ W1, const float* __restrict__ b1,
    const float* __restrict__ W2, const float* __restrict__ b2,
    float* __restrict__ out)
{
  int cnt = g_count[eid];
  int base = bid * 64;
  if (base >= cnt) return;
  float avg = g_avg[eid];
  float* Hs   = sm + SMF_HS;
  float* Wbuf = sm + SMF_WBUF;
  ull*   Adup = (ull*)(sm + SMF_ADUP);
  __shared__ int rows_m[64];
  __shared__ const float* ptab_m[128];
  int tid = threadIdx.x;
  int lane = tid & 31, rbase = (tid >> 5) * 8;
  if (tid < 64) {
    int i = base + tid;
    int row = (i < cnt) ? g_bucket[eid * B_ROWS + i] : -1;
    rows_m[tid] = row;
    size_t rr = (size_t)(row < 0 ? 0 : row) * 256;
    ptab_m[tid]      = zg + rr;
    ptab_m[64 + tid] = zi + rr;
  }
  __syncthreads();
  auto fetchCat = [&](int c, int ar, int aseg) -> float4 {
    int kc = c * CH;
    return *(const float4*)(ptab_m[((kc >> 8) << 6) + ar] + (kc & 255) + aseg);
  };
  auto fetchMul = [&](int c, int ar, int aseg) -> float4 {
    int kc = c * CH;
    float4 g = *(const float4*)(ptab_m[ar] + kc + aseg);
    float4 z = *(const float4*)(ptab_m[64 + ar] + kc + aseg);
    return make_float4(g.x * z.x, g.y * z.y, g.z * z.z, g.w * z.w);
  };
  auto fetchH = [&](int c, int ar, int aseg) -> float4 {
    return *(const float4*)(Hs + ar * 256 + c * CH + aseg);
  };
  auto fetchHW = [&](int c, int ar, int aseg) -> float4 {
    int kc = c * CH;
    float4 a = *(const float4*)(Hs + ar * 256 + kc + aseg);
    float4 g = *(const float4*)(ptab_m[ar] + kc + aseg);
    float4 z = *(const float4*)(ptab_m[64 + ar] + kc + aseg);
    return make_float4(a.x * g.x + (1.f - a.x) * z.x,
                       a.y * g.y + (1.f - a.y) * z.y,
                       a.z * g.z + (1.f - a.z) * z.z,
                       a.w * g.w + (1.f - a.w) * z.w);
  };
  ull acc[8][4];
  if (MODE == 0) {
    gemmT<64, 32>(fetchCat, W1, Adup, Wbuf, acc, rbase, lane);
    epi_smem2<8, 1>(acc, b1, Hs, rbase, lane);
    gemmT<64, 16>(fetchH, W2, Adup, Wbuf, acc, rbase, lane);
  } else if (MODE == 1) {
    gemmT<64, 16>(fetchMul, W1, Adup, Wbuf, acc, rbase, lane);
    epi_smem2<8, 1>(acc, b1, Hs, rbase, lane);
    gemmT<64, 16>(fetchH, W2, Adup, Wbuf, acc, rbase, lane);
  } else {
    gemmT<64, 32>(fetchCat, W1, Adup, Wbuf, acc, rbase, lane);
    epi_smem2<8, 2>(acc, b1, Hs, rbase, lane);   // alpha = sigmoid
    gemmT<64, 16>(fetchHW, W2, Adup, Wbuf, acc, rbase, lane);
  }
  epi_gmem2<8>(acc, b2, out, rows_m, rbase, lane, avg);
}

// attn: 64 pairs (128 token rows) per block, processed in two 64-row halves.
// Per half: Q gemm -> Qs; K gemm epilogue computes head scores vs Qs; softmax
// -> Cf. Then V gemms (per half) combine pairs into Qs region (Q dead).
// Finally Wo gemm (in-place epi into Qs) and Wfc gemm -> scatter. No gmem mid.
__device__ __forceinline__ void attn_body(
    int bid,
    const float* __restrict__ zg, const float* __restrict__ zi,
    const float* __restrict__ Wq, const float* __restrict__ bq,
    const float* __restrict__ Wk, const float* __restrict__ bk,
    const float* __restrict__ Wv, const float* __restrict__ bv,
    const float* __restrict__ Wo, const float* __restrict__ bo,
    const float* __restrict__ Wfc, const float* __restrict__ bfc,
    float* __restrict__ out)
{
  int cnt = g_count[2];
  int base = bid * 64;                   // pair base
  if (base >= cnt) return;
  float avg = g_avg[2];
  float* Qs   = sm + SMF_HS;             // 64 x 256 (Q per half; later combined rows)
  float* Wbuf = sm + SMF_WBUF;
  ull*   Adup = (ull*)(sm + SMF_ADUP);
  __shared__ const float* ptab_a[128];   // 64 pairs x 2 sides
  __shared__ int rows_a[64];
  __shared__ float sc[32][4][2][2];      // [local pair][head][t_q][t_k]
  __shared__ float Cf[64 * 8];
  int tid = threadIdx.x;
  int lane = tid & 31, rbase = (tid >> 5) * 8;
  if (tid < 128) {
    int pair = tid >> 1;
    int i = base + pair;
    int row = (i < cnt) ? g_bucket[2 * B_ROWS + i] : -1;
    if ((tid & 1) == 0) rows_a[pair] = row;
    size_t rr = (size_t)(row < 0 ? 0 : row) * 256;
    ptab_a[tid] = ((tid & 1) ? zi : zg) + rr;
  }
  __syncthreads();

  ull acc[8][4];
  // ---- per half: Q, K->scores, softmax ----
  #pragma unroll 1
  for (int h = 0; h < 2; h++) {
    auto fetchT = [&](int c, int ar, int aseg) -> float4 {
      return *(const float4*)(ptab_a[(h << 6) + ar] + c * CH + aseg);
    };
    gemmT<64, 16>(fetchT, Wq, Adup, Wbuf, acc, rbase, lane);
    epi_smem2<8, 0>(acc, bq, Qs, rbase, lane);
    gemmT<64, 16>(fetchT, Wk, Adup, Wbuf, acc, rbase, lane);
    {
      float4 bklo = *(const float4*)(bk + 4 * lane);
      float4 bkhi = *(const float4*)(bk + 4 * lane + 128);
      int g = lane >> 4;
      #pragma unroll
      for (int ri = 0; ri < 8; ri++) {
        int r = rbase + ri;
        int p = r >> 1, tk = r & 1;     // local pair in half
        float2 v0 = funpack(acc[ri][0]), v1 = funpack(acc[ri][1]);
        float2 v2 = funpack(acc[ri][2]), v3 = funpack(acc[ri][3]);
        float kl0 = v0.x + bklo.x, kl1 = v0.y + bklo.y;
        float kl2 = v1.x + bklo.z, kl3 = v1.y + bklo.w;
        float kh0 = v2.x + bkhi.x, kh1 = v2.y + bkhi.y;
        float kh2 = v3.x + bkhi.z, kh3 = v3.y + bkhi.w;
        #pragma unroll
        for (int tq = 0; tq < 2; tq++) {
          const float* q = Qs + (2 * p + tq) * 256;
          float4 qlo = *(const float4*)(q + 4 * lane);
          float4 qhi = *(const float4*)(q + 4 * lane + 128);
          float slo = kl0 * qlo.x + kl1 * qlo.y + kl2 * qlo.z + kl3 * qlo.w;
          float shi = kh0 * qhi.x + kh1 * qhi.y + kh2 * qhi.z + kh3 * qhi.w;
          #pragma unroll
          for (int off = 8; off; off >>= 1) {
            slo += __shfl_down_sync(0xffffffffu, slo, off, 16);
            shi += __shfl_down_sync(0xffffffffu, shi, off, 16);
          }
          if ((lane & 15) == 0) {
            sc[p][g][tq][tk]     = slo;   // heads 0/1
            sc[p][2 + g][tq][tk] = shi;   // heads 2/3
          }
        }
      }
    }
    __syncthreads();
    if (tid < 128) {
      int p = tid >> 2, hh = tid & 3;
      const float s = 0.125f;   // 1/sqrt(64)
      float s00 = sc[p][hh][0][0] * s, s01 = sc[p][hh][0][1] * s;
      float s10 = sc[p][hh][1][0] * s, s11 = sc[p][hh][1][1] * s;
      float m0 = fmaxf(s00, s01), m1 = fmaxf(s10, s11);
      float e00 = expf(s00 - m0), e01 = expf(s01 - m0);
      float e10 = expf(s10 - m1), e11 = expf(s11 - m1);
      float i0 = 1.f / (e00 + e01), i1 = 1.f / (e10 + e11);
      int gp = (h << 5) + p;    // global pair in block
      Cf[gp * 8 + hh * 2 + 0] = 0.5f * (e00 * i0 + e10 * i1);
      Cf[gp * 8 + hh * 2 + 1] = 0.5f * (e01 * i0 + e11 * i1);
    }
    __syncthreads();
  }

  // ---- V per half; combine pairs -> Qs (combined rows, pair-indexed) ----
  #pragma unroll 1
  for (int h = 0; h < 2; h++) {
    auto fetchT = [&](int c, int ar, int aseg) -> float4 {
      return *(const float4*)(ptab_a[(h << 6) + ar] + c * CH + aseg);
    };
    gemmT<64, 16>(fetchT, Wv, Adup, Wbuf, acc, rbase, lane);
    {
      float4 bvlo = *(const float4*)(bv + 4 * lane);
      float4 bvhi = *(const float4*)(bv + 4 * lane + 128);
      int hlo = lane >> 4, hhi = 2 + (lane >> 4);
      #pragma unroll
      for (int q = 0; q < 4; q++) {
        int p = (rbase >> 1) + q;        // local pair
        int gp = (h << 5) + p;           // global pair in block
        float c0l = Cf[gp * 8 + hlo * 2 + 0], c1l = Cf[gp * 8 + hlo * 2 + 1];
        float c0h = Cf[gp * 8 + hhi * 2 + 0], c1h = Cf[gp * 8 + hhi * 2 + 1];
        float2 a00 = funpack(acc[2 * q][0]),     a01 = funpack(acc[2 * q][1]);
        float2 a02 = funpack(acc[2 * q][2]),     a03 = funpack(acc[2 * q][3]);
        float2 a10 = funpack(acc[2 * q + 1][0]), a11 = funpack(acc[2 * q + 1][1]);
        float2 a12 = funpack(acc[2 * q + 1][2]), a13 = funpack(acc[2 * q + 1][3]);
        // coefs sum to 1 -> bias passes straight through
        float4 lo = make_float4(c0l * a00.x + c1l * a10.x + bvlo.x,
                                c0l * a00.y + c1l * a10.y + bvlo.y,
                                c0l * a01.x + c1l * a11.x + bvlo.z,
                                c0l * a01.y + c1l * a11.y + bvlo.w);
        float4 hi = make_float4(c0h * a02.x + c1h * a12.x + bvhi.x,
                                c0h * a02.y + c1h * a12.y + bvhi.y,
                                c0h * a03.x + c1h * a13.x + bvhi.z,
                                c0h * a03.y + c1h * a13.y + bvhi.w);
        // NOTE: half 0 writes Qs rows 0..31 while half 1's Q phase is done;
        // Qs as Q is dead after the score loops above.
        *(float4*)(Qs + gp * 256 + 4 * lane) = lo;
        *(float4*)(Qs + gp * 256 + 4 * lane + 128) = hi;
      }
    }
    __syncthreads();
  }

  // ---- Wo gemm on 64 combined rows; in-place epi; Wfc gemm; scatter ----
  auto fetchMs = [&](int c, int ar, int aseg) -> float4 {
    return *(const float4*)(Qs + ar * 256 + c * CH + aseg);
  };
  gemmT<64, 16>(fetchMs, Wo, Adup, Wbuf, acc, rbase, lane);
  epi_smem2<8, 0>(acc, bo, Qs, rbase, lane);   // in place: gemm fully drained
  gemmT<64, 16>(fetchMs, Wfc, Adup, Wbuf, acc, rbase, lane);
  epi_gmem2<8>(acc, bfc, out, rows_a, rbase, lane, avg);
}

// ---------------- fused expert kernel --------------------------------------
#define NB_ATTN  (B_ROWS / 64)          // 2048
#define NB_MLP   (B_ROWS / 64)          // 2048

__global__ void __launch_bounds__(256, 2) k_experts(
    const float* __restrict__ zg, const float* __restrict__ zi,
    const float* __restrict__ cW1, const float* __restrict__ cb1,
    const float* __restrict__ cW2, const float* __restrict__ cb2,
    const float* __restrict__ mW1, const float* __restrict__ mb1,
    const float* __restrict__ mW2, const float* __restrict__ mb2,
    const float* __restrict__ aWq, const float* __restrict__ abq,
    const float* __restrict__ aWk, const float* __restrict__ abk,
    const float* __restrict__ aWv, const float* __restrict__ abv,
    const float* __restrict__ aWo, const float* __restrict__ abo,
    const float* __restrict__ aWfc, const float* __restrict__ abfc,
    const float* __restrict__ wWa, const float* __restrict__ wba,
    const float* __restrict__ wWo, const float* __restrict__ wbo,
    float* __restrict__ out)
{
  int b = blockIdx.x;
  if (b < NB_ATTN) {
    attn_body(b, zg, zi, aWq, abq, aWk, abk, aWv, abv, aWo, abo, aWfc, abfc, out);
  } else if (b < NB_ATTN + NB_MLP) {
    mlp_body<0>(b - NB_ATTN, 0, zg, zi, cW1, cb1, cW2, cb2, out);
  } else if (b < NB_ATTN + 2 * NB_MLP) {
    mlp_body<1>(b - NB_ATTN - NB_MLP, 1, zg, zi, mW1, mb1, mW2, mb2, out);
  } else {
    mlp_body<2>(b - NB_ATTN - 2 * NB_MLP, 3, zg, zi, wWa, wba, wWo, wbo, out);
  }
}

// ---------------- launch ---------------------------------------------------
extern "C" void kernel_launch(void* const* d_in, const int* in_sizes, int n_in,
                              void* d_out, int out_size) {
  (void)in_sizes; (void)n_in;
  const float* zg  = (const float*)d_in[0];
  const float* zi  = (const float*)d_in[1];
  const float* gW  = (const float*)d_in[2];
  const float* gb  = (const float*)d_in[3];
  const float* cW1 = (const float*)d_in[4];
  const float* cb1 = (const float*)d_in[5];
  const float* cW2 = (const float*)d_in[6];
  const float* cb2 = (const float*)d_in[7];
  const float* mW1 = (const float*)d_in[8];
  const float* mb1 = (const float*)d_in[9];
  const float* mW2 = (const float*)d_in[10];
  const float* mb2 = (const float*)d_in[11];
  const float* aWq = (const float*)d_in[12];
  const float* abq = (const float*)d_in[13];
  const float* aWk = (const float*)d_in[14];
  const float* abk = (const float*)d_in[15];
  const float* aWv = (const float*)d_in[16];
  const float* abv = (const float*)d_in[17];
  const float* aWo = (const float*)d_in[18];
  const float* abo = (const float*)d_in[19];
  const float* aWfc = (const float*)d_in[20];
  const float* abfc = (const float*)d_in[21];
  const float* wWa = (const float*)d_in[22];
  const float* wba = (const float*)d_in[23];
  const float* wWo = (const float*)d_in[24];
  const float* wbo = (const float*)d_in[25];
  float* out = (float*)d_out;

  const int SM_EXP = (16384 + 8192 + 2048) * 4;   // 106496 B

  cudaFuncSetAttribute(k_experts, cudaFuncAttributeMaxDynamicSharedMemorySize, SM_EXP);

  k_reset<<<1, 32>>>();
  k_gate<<<B_ROWS / 8, 256>>>(zg, zi, gW, gb);
  k_finalize<<<1, 32>>>(out, out_size);
  k_experts<<<NB_ATTN + 3 * NB_MLP, 256, SM_EXP>>>(
      zg, zi, cW1, cb1, cW2, cb2, mW1, mb1, mW2, mb2,
      aWq, abq, aWk, abk, aWv, abv, aWo, abo, aWfc, abfc,
      wWa, wba, wWo, wbo, out);
}